// round 14
// baseline (speedup 1.0000x reference)
#include <cuda_runtime.h>
#include <cuda_fp16.h>
#include <cstdint>

#define V_    50257
#define VPAD  50304
#define NVB   393          // vocab blocks
#define BS_   512
#define D_    512
#define BM    128
#define BN    256
#define BKF   64
#define NCH   (D_/BKF)

__device__ __align__(16) uint2 g_pnh2[BS_*D_/4];        // pn fp16 pairs [t][k/4]
__device__ __align__(16) __half g_embh[(size_t)VPAD*D_]; // emb fp16 (rows >= V_ stay 0)
__device__ float g_inv_enorm[VPAD];
__device__ float g_sim_scratch[(size_t)BS_*V_];
__device__ float g_part_s[BS_*NVB];
__device__ int   g_part_i[BS_*NVB];

#define SW128(x) ((x) ^ (((x) >> 3) & 0x70))

__device__ __forceinline__ uint32_t smem_u32(const void* p){
    uint32_t a;
    asm("{ .reg .u64 t; cvta.to.shared.u64 t, %1; cvt.u32.u64 %0, t; }" : "=r"(a) : "l"(p));
    return a;
}
__device__ __forceinline__ uint32_t f16x2_of(float lo, float hi){
    __half2 h = __floats2half2_rn(lo, hi);
    return *(uint32_t*)&h;
}
__device__ __forceinline__ void ldsm4(uint32_t* r, uint32_t addr){
    asm volatile("ldmatrix.sync.aligned.m8n8.x4.shared.b16 {%0,%1,%2,%3}, [%4];"
        : "=r"(r[0]), "=r"(r[1]), "=r"(r[2]), "=r"(r[3]) : "r"(addr));
}
#define MMA16816(c, a, b0v, b1v) \
    asm volatile("mma.sync.aligned.m16n8k16.row.col.f32.f16.f16.f32 " \
        "{%0,%1,%2,%3}, {%4,%5,%6,%7}, {%8,%9}, {%0,%1,%2,%3};" \
        : "+f"((c)[0]), "+f"((c)[1]), "+f"((c)[2]), "+f"((c)[3]) \
        : "r"((a)[0]), "r"((a)[1]), "r"((a)[2]), "r"((a)[3]), "r"(b0v), "r"(b1v))
#define CPASYNC16(dst, src) \
    asm volatile("cp.async.cg.shared.global [%0], [%1], 16;" :: "r"(dst), "l"(src))
#define CPCOMMIT() asm volatile("cp.async.commit_group;" ::: "memory")
#define CPWAIT0()  asm volatile("cp.async.wait_group 0;" ::: "memory")

// ---------------- kernel 1: perturb + normalize + fp16 ----------------
__global__ void prep_kernel(const int* __restrict__ utt, const float* __restrict__ emb,
                            const float* __restrict__ grad) {
    const int t = blockIdx.x, tid = threadIdx.x;  // 128 threads
    const int token = utt[t];
    float4 e = *(const float4*)(emb + (size_t)token * D_ + tid * 4);
    float4 g = *(const float4*)(grad + (size_t)t * D_ + tid * 4);
    float p0 = e.x + 0.4f * ((g.x > 0.f) ? 1.f : ((g.x < 0.f) ? -1.f : 0.f));
    float p1 = e.y + 0.4f * ((g.y > 0.f) ? 1.f : ((g.y < 0.f) ? -1.f : 0.f));
    float p2 = e.z + 0.4f * ((g.z > 0.f) ? 1.f : ((g.z < 0.f) ? -1.f : 0.f));
    float p3 = e.w + 0.4f * ((g.w > 0.f) ? 1.f : ((g.w < 0.f) ? -1.f : 0.f));
    float ss = p0*p0 + p1*p1 + p2*p2 + p3*p3;
#pragma unroll
    for (int off = 16; off; off >>= 1) ss += __shfl_xor_sync(0xffffffffu, ss, off);
    __shared__ float wsum[4];
    if ((tid & 31) == 0) wsum[tid >> 5] = ss;
    __syncthreads();
    float inv = 1.f / fmaxf(sqrtf(wsum[0] + wsum[1] + wsum[2] + wsum[3]), 1e-8f);
    p0 *= inv; p1 *= inv; p2 *= inv; p3 *= inv;
    g_pnh2[t * 128 + tid] = make_uint2(f16x2_of(p0, p1), f16x2_of(p2, p3));
}

// ---------------- kernel 2: emb -> fp16 + inverse norms (one pass) ----------------
__global__ void conv_kernel(const float* __restrict__ emb) {
    const int row = blockIdx.x * 8 + (threadIdx.x >> 5);   // 256 threads, 8 rows/block
    const int lane = threadIdx.x & 31;
    if (row >= V_) return;
    const float4* src = (const float4*)(emb + (size_t)row * D_ + lane * 16);
    float4 a = src[0], b = src[1], c = src[2], d = src[3];
    float ss = a.x*a.x + a.y*a.y + a.z*a.z + a.w*a.w
             + b.x*b.x + b.y*b.y + b.z*b.z + b.w*b.w
             + c.x*c.x + c.y*c.y + c.z*c.z + c.w*c.w
             + d.x*d.x + d.y*d.y + d.z*d.z + d.w*d.w;
    uint4 o0, o1;
    o0.x = f16x2_of(a.x, a.y); o0.y = f16x2_of(a.z, a.w);
    o0.z = f16x2_of(b.x, b.y); o0.w = f16x2_of(b.z, b.w);
    o1.x = f16x2_of(c.x, c.y); o1.y = f16x2_of(c.z, c.w);
    o1.z = f16x2_of(d.x, d.y); o1.w = f16x2_of(d.z, d.w);
    uint4* dst = (uint4*)((char*)g_embh + (size_t)row * 1024 + lane * 32);
    dst[0] = o0; dst[1] = o1;
#pragma unroll
    for (int off = 16; off; off >>= 1) ss += __shfl_xor_sync(0xffffffffu, ss, off);
    if (lane == 0) g_inv_enorm[row] = 1.f / fmaxf(sqrtf(ss), 1e-8f);
}

// ---------------- kernel 3: fp16 GEMM 128x256 tile + fused argmax ----
__global__ void __launch_bounds__(512, 1) gemm_kernel(float* __restrict__ simout,
                                                      const float* __restrict__ noise) {
    extern __shared__ char smem[];
    const uint32_t sb = smem_u32(smem);
    const int tid = threadIdx.x;
    const int wid = tid >> 5, lane = tid & 31;
    const int tblk = blockIdx.x * BN;
    const int vblk = blockIdx.y * BM;

    // smem: stage s at s*49152: A 16KB then B 32KB. sInv @98304.
    float acc[2][8][4];
#pragma unroll
    for (int i = 0; i < 2; i++)
#pragma unroll
        for (int j = 0; j < 8; j++)
#pragma unroll
            for (int q = 0; q < 4; q++) acc[i][j][q] = 0.f;

    const int mw = (wid >> 2) * 32;
    const int nw = (wid & 3) * 64;
    const int a_row = (lane & 7) + ((lane >> 3) & 1) * 8;
    const int a_kb  = ((lane >> 4) & 1) * 16;
    const int b_row = (lane & 7) + ((lane >> 4) & 1) * 8;
    const int b_kb  = ((lane >> 3) & 1) * 16;

    const int lrow = tid >> 3;          // 0..63
    const int lseg = tid & 7;

    // ---- preamble: chunk 0 into stage 0 ----
#pragma unroll
    for (int r = 0; r < 2; r++) {
        int row = lrow + 64 * r;
        uint32_t soff = SW128((uint32_t)(row * 128 + lseg * 16));
        CPASYNC16(sb + soff,
                  (const char*)g_embh + (size_t)(vblk + row) * 1024 + lseg * 16);
    }
#pragma unroll
    for (int r = 0; r < 4; r++) {
        int row = lrow + 64 * r;
        uint32_t soff = SW128((uint32_t)(row * 128 + lseg * 16));
        CPASYNC16(sb + 16384 + soff,
                  (const char*)g_pnh2 + (size_t)(tblk + row) * 1024 + lseg * 16);
    }
    CPCOMMIT();

    for (int c = 0; c < NCH; c++) {
        const int bb = c & 1;
        CPWAIT0();
        __syncthreads();                 // chunk c ready; compute(c-1) done everywhere
        if (c < NCH - 1) {
            const uint32_t nb = (uint32_t)((bb ^ 1) * 49152);
            const size_t kbyte = (size_t)(c + 1) * 128;
#pragma unroll
            for (int r = 0; r < 2; r++) {
                int row = lrow + 64 * r;
                uint32_t soff = SW128((uint32_t)(row * 128 + lseg * 16));
                CPASYNC16(sb + nb + soff,
                          (const char*)g_embh + (size_t)(vblk + row) * 1024 + kbyte + lseg * 16);
            }
#pragma unroll
            for (int r = 0; r < 4; r++) {
                int row = lrow + 64 * r;
                uint32_t soff = SW128((uint32_t)(row * 128 + lseg * 16));
                CPASYNC16(sb + nb + 16384 + soff,
                          (const char*)g_pnh2 + (size_t)(tblk + row) * 1024 + kbyte + lseg * 16);
            }
            CPCOMMIT();
        }
        const uint32_t AB = (uint32_t)(bb * 49152), BB = AB + 16384;
#pragma unroll
        for (int s = 0; s < 4; s++) {
            const uint32_t akoff = (uint32_t)(s * 32 + a_kb);
            const uint32_t bkoff = (uint32_t)(s * 32 + b_kb);
            uint32_t ah[8], bh[16];
#pragma unroll
            for (int i = 0; i < 2; i++)
                ldsm4(&ah[i*4], sb + AB + SW128((uint32_t)((mw + i*16 + a_row) * 128) + akoff));
#pragma unroll
            for (int j2 = 0; j2 < 4; j2++)
                ldsm4(&bh[j2*4], sb + BB + SW128((uint32_t)((nw + j2*16 + b_row) * 128) + bkoff));
#pragma unroll
            for (int i = 0; i < 2; i++)
#pragma unroll
                for (int j = 0; j < 8; j++)
                    MMA16816(acc[i][j], &ah[i*4], bh[(j>>1)*4 + (j&1)*2], bh[(j>>1)*4 + (j&1)*2 + 1]);
        }
    }
    __syncthreads();

    // ---- inv norms into smem ----
    float* sInv = (float*)(smem + 98304);
    if (tid < 128) sInv[tid] = g_inv_enorm[vblk + tid];
    __syncthreads();

    // ---- epilogue: 4 phases x 64 tokens, staged through smem, fused argmax ----
    float* cs = (float*)smem;              // [64][132] floats = 33792 B
    const int v4 = lane * 4;
    for (int p = 0; p < 4; p++) {
        __syncthreads();
        if (nw == p * 64) {
#pragma unroll
            for (int i = 0; i < 2; i++)
#pragma unroll
                for (int j = 0; j < 8; j++) {
                    int v0 = mw + i * 16 + (lane >> 2);
                    int tl = j * 8 + (lane & 3) * 2;
                    cs[ tl      * 132 + v0    ] = acc[i][j][0];
                    cs[(tl + 1) * 132 + v0    ] = acc[i][j][1];
                    cs[ tl      * 132 + v0 + 8] = acc[i][j][2];
                    cs[(tl + 1) * 132 + v0 + 8] = acc[i][j][3];
                }
        }
        __syncthreads();
#pragma unroll
        for (int it = 0; it < 4; it++) {
            int tl = (tid >> 5) + it * 16;
            int gt = tblk + p * 64 + tl;
            float4 val = *(float4*)(cs + tl * 132 + v4);
            val.x *= sInv[v4];
            val.y *= sInv[v4 + 1];
            val.z *= sInv[v4 + 2];
            val.w *= sInv[v4 + 3];
            int gv = vblk + v4;
            // scalar stores: sim row base gt*V_ only 4B aligned (V_ odd)
            float* dst = simout + (size_t)gt * V_ + gv;
            if (gv     < V_) dst[0] = val.x;
            if (gv + 1 < V_) dst[1] = val.y;
            if (gv + 2 < V_) dst[2] = val.z;
            if (gv + 3 < V_) dst[3] = val.w;
            // fused partial argmax over this CTA's 128 v for token gt
            const float* nrow = noise + (size_t)gt * V_;
            float fs = -3e38f; int fv = 0;
            float e[4] = {val.x, val.y, val.z, val.w};
#pragma unroll
            for (int u = 0; u < 4; u++) {
                float sv = (gv + u < V_) ? e[u] : -3e38f;
                if (sv > fs) { fs = sv; fv = gv + u; }
                else if (sv == fs && sv > -3e38f) {
                    float n1 = nrow[fv], n2 = nrow[gv + u];
                    if (n2 > n1) fv = gv + u;
                }
            }
#pragma unroll
            for (int off = 16; off; off >>= 1) {
                float os = __shfl_xor_sync(0xffffffffu, fs, off);
                int   ov = __shfl_xor_sync(0xffffffffu, fv, off);
                bool take = os > fs;
                if (!take && os == fs && os > -3e38f) {
                    float n1 = nrow[fv], n2 = nrow[ov];
                    take = (n2 > n1) || (n2 == n1 && ov < fv);
                }
                if (take) { fs = os; fv = ov; }
            }
            if (lane == 0) {
                g_part_s[gt * NVB + blockIdx.y] = fs;
                g_part_i[gt * NVB + blockIdx.y] = fv;
            }
        }
    }
}

// ---------------- kernel 4: merge partials ----------------
__global__ void merge_kernel(const float* __restrict__ noise,
                             void* __restrict__ out, int write_float) {
    const int t = blockIdx.x, tid = threadIdx.x;   // 128 threads
    const float* ps = g_part_s + t * NVB;
    const int*   pi = g_part_i + t * NVB;

    float s = -3e38f;
    for (int j = tid; j < NVB; j += 128) s = fmaxf(s, ps[j]);
#pragma unroll
    for (int off = 16; off; off >>= 1) s = fmaxf(s, __shfl_xor_sync(0xffffffffu, s, off));
    __shared__ float sm[4];
    if ((tid & 31) == 0) sm[tid >> 5] = s;
    __syncthreads();
    float smax = fmaxf(fmaxf(sm[0], sm[1]), fmaxf(sm[2], sm[3]));

    const float* nrow = noise + (size_t)t * V_;
    float bn = -2.f; int bv = 0x7fffffff;
    for (int j = tid; j < NVB; j += 128) {
        if (ps[j] == smax) {
            int v = pi[j];
            float n = nrow[v];
            if (n > bn || (n == bn && v < bv)) { bn = n; bv = v; }
        }
    }
#pragma unroll
    for (int off = 16; off; off >>= 1) {
        float on = __shfl_xor_sync(0xffffffffu, bn, off);
        int   ov = __shfl_xor_sync(0xffffffffu, bv, off);
        if (on > bn || (on == bn && ov < bv)) { bn = on; bv = ov; }
    }
    __shared__ float nm[4]; __shared__ int vm[4];
    if ((tid & 31) == 0) { nm[tid >> 5] = bn; vm[tid >> 5] = bv; }
    __syncthreads();
    if (tid == 0) {
#pragma unroll
        for (int w = 1; w < 4; w++) {
            if (nm[w] > nm[0] || (nm[w] == nm[0] && vm[w] < vm[0])) { nm[0] = nm[w]; vm[0] = vm[w]; }
        }
        if (write_float) ((float*)out)[t] = (float)vm[0];
        else             ((int*)out)[t]   = vm[0];
    }
}

// ---------------- launcher ----------------
extern "C" void kernel_launch(void* const* d_in, const int* in_sizes, int n_in,
                              void* d_out, int out_size) {
    const int*   utt   = (const int*)d_in[0];
    const float* emb   = (const float*)d_in[1];
    const float* grad  = (const float*)d_in[2];
    const float* noise = (const float*)d_in[3];

    prep_kernel<<<BS_, 128>>>(utt, emb, grad);
    conv_kernel<<<(V_ + 7) / 8, 256>>>(emb);

    const long long SIMN = (long long)BS_ * V_;
    float* simptr;
    float* simscr;
    cudaGetSymbolAddress((void**)&simscr, g_sim_scratch);
    if ((long long)out_size == SIMN + BS_)      simptr = (float*)d_out + BS_;
    else if ((long long)out_size == SIMN)       simptr = (float*)d_out;
    else                                        simptr = simscr;

    cudaFuncSetAttribute(gemm_kernel, cudaFuncAttributeMaxDynamicSharedMemorySize, 98816);
    dim3 grid(BS_ / BN, NVB);
    gemm_kernel<<<grid, 512, 98816>>>(simptr, noise);

    if ((long long)out_size == SIMN + BS_)
        merge_kernel<<<BS_, 128>>>(noise, d_out, 1);
    else if (out_size == BS_)
        merge_kernel<<<BS_, 128>>>(noise, d_out, 0);
}

// round 15
// speedup vs baseline: 1.1320x; 1.1320x over previous
#include <cuda_runtime.h>
#include <cuda_fp16.h>
#include <cstdint>

#define V_    50257
#define VPAD  50304
#define NVB   393          // vocab blocks
#define BS_   512
#define D_    512
#define BM    128
#define BN    128
#define BKF   64
#define NCH   (D_/BKF)

__device__ __align__(16) uint2 g_pnh2[BS_*D_/4];        // pn fp16 pairs [t][k/4]
__device__ __align__(16) __half g_embh[(size_t)VPAD*D_]; // emb fp16 (rows >= V_ stay 0)
__device__ float g_inv_enorm[VPAD];
__device__ float g_sim_scratch[(size_t)BS_*V_];
__device__ float g_part_s[BS_*NVB];
__device__ int   g_part_i[BS_*NVB];

#define SW128(x) ((x) ^ (((x) >> 3) & 0x70))

__device__ __forceinline__ uint32_t smem_u32(const void* p){
    uint32_t a;
    asm("{ .reg .u64 t; cvta.to.shared.u64 t, %1; cvt.u32.u64 %0, t; }" : "=r"(a) : "l"(p));
    return a;
}
__device__ __forceinline__ uint32_t f16x2_of(float lo, float hi){
    __half2 h = __floats2half2_rn(lo, hi);
    return *(uint32_t*)&h;
}
__device__ __forceinline__ void ldsm4(uint32_t* r, uint32_t addr){
    asm volatile("ldmatrix.sync.aligned.m8n8.x4.shared.b16 {%0,%1,%2,%3}, [%4];"
        : "=r"(r[0]), "=r"(r[1]), "=r"(r[2]), "=r"(r[3]) : "r"(addr));
}
#define MMA16816(c, a, b0v, b1v) \
    asm volatile("mma.sync.aligned.m16n8k16.row.col.f32.f16.f16.f32 " \
        "{%0,%1,%2,%3}, {%4,%5,%6,%7}, {%8,%9}, {%0,%1,%2,%3};" \
        : "+f"((c)[0]), "+f"((c)[1]), "+f"((c)[2]), "+f"((c)[3]) \
        : "r"((a)[0]), "r"((a)[1]), "r"((a)[2]), "r"((a)[3]), "r"(b0v), "r"(b1v))
#define CPASYNC16(dst, src) \
    asm volatile("cp.async.cg.shared.global [%0], [%1], 16;" :: "r"(dst), "l"(src))
#define CPCOMMIT() asm volatile("cp.async.commit_group;" ::: "memory")
#define CPWAIT0()  asm volatile("cp.async.wait_group 0;" ::: "memory")
#define CPWAIT1()  asm volatile("cp.async.wait_group 1;" ::: "memory")

// ---------------- kernel 1: perturb + normalize + fp16 ----------------
__global__ void prep_kernel(const int* __restrict__ utt, const float* __restrict__ emb,
                            const float* __restrict__ grad) {
    const int t = blockIdx.x, tid = threadIdx.x;  // 128 threads
    const int token = utt[t];
    float4 e = *(const float4*)(emb + (size_t)token * D_ + tid * 4);
    float4 g = *(const float4*)(grad + (size_t)t * D_ + tid * 4);
    float p0 = e.x + 0.4f * ((g.x > 0.f) ? 1.f : ((g.x < 0.f) ? -1.f : 0.f));
    float p1 = e.y + 0.4f * ((g.y > 0.f) ? 1.f : ((g.y < 0.f) ? -1.f : 0.f));
    float p2 = e.z + 0.4f * ((g.z > 0.f) ? 1.f : ((g.z < 0.f) ? -1.f : 0.f));
    float p3 = e.w + 0.4f * ((g.w > 0.f) ? 1.f : ((g.w < 0.f) ? -1.f : 0.f));
    float ss = p0*p0 + p1*p1 + p2*p2 + p3*p3;
#pragma unroll
    for (int off = 16; off; off >>= 1) ss += __shfl_xor_sync(0xffffffffu, ss, off);
    __shared__ float wsum[4];
    if ((tid & 31) == 0) wsum[tid >> 5] = ss;
    __syncthreads();
    float inv = 1.f / fmaxf(sqrtf(wsum[0] + wsum[1] + wsum[2] + wsum[3]), 1e-8f);
    p0 *= inv; p1 *= inv; p2 *= inv; p3 *= inv;
    g_pnh2[t * 128 + tid] = make_uint2(f16x2_of(p0, p1), f16x2_of(p2, p3));
}

// ---------------- kernel 2: emb -> fp16 + inverse norms (one pass) ----------------
__global__ void conv_kernel(const float* __restrict__ emb) {
    const int row = blockIdx.x * 8 + (threadIdx.x >> 5);   // 256 threads, 8 rows/block
    const int lane = threadIdx.x & 31;
    if (row >= V_) return;
    const float4* src = (const float4*)(emb + (size_t)row * D_ + lane * 16);
    float4 a = src[0], b = src[1], c = src[2], d = src[3];
    float ss = a.x*a.x + a.y*a.y + a.z*a.z + a.w*a.w
             + b.x*b.x + b.y*b.y + b.z*b.z + b.w*b.w
             + c.x*c.x + c.y*c.y + c.z*c.z + c.w*c.w
             + d.x*d.x + d.y*d.y + d.z*d.z + d.w*d.w;
    uint4 o0, o1;
    o0.x = f16x2_of(a.x, a.y); o0.y = f16x2_of(a.z, a.w);
    o0.z = f16x2_of(b.x, b.y); o0.w = f16x2_of(b.z, b.w);
    o1.x = f16x2_of(c.x, c.y); o1.y = f16x2_of(c.z, c.w);
    o1.z = f16x2_of(d.x, d.y); o1.w = f16x2_of(d.z, d.w);
    uint4* dst = (uint4*)((char*)g_embh + (size_t)row * 1024 + lane * 32);
    dst[0] = o0; dst[1] = o1;
#pragma unroll
    for (int off = 16; off; off >>= 1) ss += __shfl_xor_sync(0xffffffffu, ss, off);
    if (lane == 0) g_inv_enorm[row] = 1.f / fmaxf(sqrtf(ss), 1e-8f);
}

// ---------------- kernel 3: fp16 GEMM, 3-stage pipeline, fused argmax ----
__global__ void __launch_bounds__(512, 2) gemm_kernel(float* __restrict__ simout,
                                                      const float* __restrict__ noise) {
    extern __shared__ char smem[];
    const uint32_t sb = smem_u32(smem);
    const int tid = threadIdx.x;
    const int wid = tid >> 5, lane = tid & 31;
    const int tblk = blockIdx.x * BN;
    const int vblk = blockIdx.y * BM;

    // smem: stage s @ s*32768 (A 16KB, B 16KB), s=0..2 ; sInv @98304 ; cs reuses 0..67583
    float acc[2][4][4];
#pragma unroll
    for (int i = 0; i < 2; i++)
#pragma unroll
        for (int j = 0; j < 4; j++)
#pragma unroll
            for (int q = 0; q < 4; q++) acc[i][j][q] = 0.f;

    const int mw = (wid >> 2) * 32;
    const int nw = (wid & 3) * 32;
    const int a_row = (lane & 7) + ((lane >> 3) & 1) * 8;
    const int a_kb  = ((lane >> 4) & 1) * 16;
    const int b_row = (lane & 7) + ((lane >> 4) & 1) * 8;
    const int b_kb  = ((lane >> 3) & 1) * 16;

    const int lrow = tid >> 3;          // 0..63
    const int lseg = tid & 7;
    const uint32_t soff0 = SW128((uint32_t)(lrow * 128 + lseg * 16));
    const uint32_t soff1 = SW128((uint32_t)((lrow + 64) * 128 + lseg * 16));
    const size_t abase0 = (size_t)(vblk + lrow) * 1024 + lseg * 16;
    const size_t abase1 = (size_t)(vblk + lrow + 64) * 1024 + lseg * 16;
    const size_t bbase0 = (size_t)(tblk + lrow) * 1024 + lseg * 16;
    const size_t bbase1 = (size_t)(tblk + lrow + 64) * 1024 + lseg * 16;

    // ---- preamble: issue chunks 0 and 1 into stages 0 and 1 ----
#pragma unroll
    for (int pc = 0; pc < 2; pc++) {
        const uint32_t st = (uint32_t)(pc * 32768);
        const size_t kb = (size_t)pc * 128;
        CPASYNC16(sb + st + soff0,         (const char*)g_embh + abase0 + kb);
        CPASYNC16(sb + st + soff1,         (const char*)g_embh + abase1 + kb);
        CPASYNC16(sb + st + 16384 + soff0, (const char*)g_pnh2 + bbase0 + kb);
        CPASYNC16(sb + st + 16384 + soff1, (const char*)g_pnh2 + bbase1 + kb);
        CPCOMMIT();
    }

#pragma unroll
    for (int c = 0; c < NCH; c++) {
        if (c == NCH - 1) { CPWAIT0(); } else { CPWAIT1(); }
        __syncthreads();                 // chunk c ready; all warps past compute(c-1)
        if (c + 2 < NCH) {
            const uint32_t nb = (uint32_t)(((c + 2) % 3) * 32768);
            const size_t kb = (size_t)(c + 2) * 128;
            CPASYNC16(sb + nb + soff0,         (const char*)g_embh + abase0 + kb);
            CPASYNC16(sb + nb + soff1,         (const char*)g_embh + abase1 + kb);
            CPASYNC16(sb + nb + 16384 + soff0, (const char*)g_pnh2 + bbase0 + kb);
            CPASYNC16(sb + nb + 16384 + soff1, (const char*)g_pnh2 + bbase1 + kb);
            CPCOMMIT();
        }
        const uint32_t AB = (uint32_t)((c % 3) * 32768), BB = AB + 16384;
#pragma unroll
        for (int s = 0; s < 4; s++) {
            const uint32_t akoff = (uint32_t)(s * 32 + a_kb);
            const uint32_t bkoff = (uint32_t)(s * 32 + b_kb);
            uint32_t ah[8], bh[8];
#pragma unroll
            for (int i = 0; i < 2; i++)
                ldsm4(&ah[i*4], sb + AB + SW128((uint32_t)((mw + i*16 + a_row) * 128) + akoff));
#pragma unroll
            for (int j2 = 0; j2 < 2; j2++)
                ldsm4(&bh[j2*4], sb + BB + SW128((uint32_t)((nw + j2*16 + b_row) * 128) + bkoff));
#pragma unroll
            for (int i = 0; i < 2; i++)
#pragma unroll
                for (int j = 0; j < 4; j++)
                    MMA16816(acc[i][j], &ah[i*4], bh[(j>>1)*4 + (j&1)*2], bh[(j>>1)*4 + (j&1)*2 + 1]);
        }
    }
    __syncthreads();                     // all compute done before smem reuse

    // ---- inv norms + full C tile staged in one pass ----
    float* sInv = (float*)(smem + 98304);
    if (tid < 128) sInv[tid] = g_inv_enorm[vblk + tid];
    float* cs = (float*)smem;            // [128][132] floats = 67584 B
#pragma unroll
    for (int i = 0; i < 2; i++)
#pragma unroll
        for (int j = 0; j < 4; j++) {
            int v0 = mw + i * 16 + (lane >> 2);
            int tl = nw + j * 8 + (lane & 3) * 2;
            cs[ tl      * 132 + v0    ] = acc[i][j][0];
            cs[(tl + 1) * 132 + v0    ] = acc[i][j][1];
            cs[ tl      * 132 + v0 + 8] = acc[i][j][2];
            cs[(tl + 1) * 132 + v0 + 8] = acc[i][j][3];
        }
    __syncthreads();

    // ---- store + fused partial argmax: 8 iters x 16 token-rows ----
    const int v4 = lane * 4;
#pragma unroll
    for (int it = 0; it < 8; it++) {
        int tl = (tid >> 5) + it * 16;
        int gt = tblk + tl;
        float4 val = *(float4*)(cs + tl * 132 + v4);
        val.x *= sInv[v4];
        val.y *= sInv[v4 + 1];
        val.z *= sInv[v4 + 2];
        val.w *= sInv[v4 + 3];
        int gv = vblk + v4;
        // scalar stores: sim row base gt*V_ only 4B aligned (V_ odd)
        float* dst = simout + (size_t)gt * V_ + gv;
        if (gv     < V_) dst[0] = val.x;
        if (gv + 1 < V_) dst[1] = val.y;
        if (gv + 2 < V_) dst[2] = val.z;
        if (gv + 3 < V_) dst[3] = val.w;
        // fused partial argmax over this CTA's 128 v for token gt
        const float* nrow = noise + (size_t)gt * V_;
        float fs = -3e38f; int fv = 0;
        float e[4] = {val.x, val.y, val.z, val.w};
#pragma unroll
        for (int u = 0; u < 4; u++) {
            float sv = (gv + u < V_) ? e[u] : -3e38f;
            if (sv > fs) { fs = sv; fv = gv + u; }
            else if (sv == fs && sv > -3e38f) {
                float n1 = nrow[fv], n2 = nrow[gv + u];
                if (n2 > n1) fv = gv + u;
            }
        }
#pragma unroll
        for (int off = 16; off; off >>= 1) {
            float os = __shfl_xor_sync(0xffffffffu, fs, off);
            int   ov = __shfl_xor_sync(0xffffffffu, fv, off);
            bool take = os > fs;
            if (!take && os == fs && os > -3e38f) {
                float n1 = nrow[fv], n2 = nrow[ov];
                take = (n2 > n1) || (n2 == n1 && ov < fv);
            }
            if (take) { fs = os; fv = ov; }
        }
        if (lane == 0) {
            g_part_s[gt * NVB + blockIdx.y] = fs;
            g_part_i[gt * NVB + blockIdx.y] = fv;
        }
    }
}

// ---------------- kernel 4: merge partials ----------------
__global__ void merge_kernel(const float* __restrict__ noise,
                             void* __restrict__ out, int write_float) {
    const int t = blockIdx.x, tid = threadIdx.x;   // 128 threads
    const float* ps = g_part_s + t * NVB;
    const int*   pi = g_part_i + t * NVB;

    float s = -3e38f;
    for (int j = tid; j < NVB; j += 128) s = fmaxf(s, ps[j]);
#pragma unroll
    for (int off = 16; off; off >>= 1) s = fmaxf(s, __shfl_xor_sync(0xffffffffu, s, off));
    __shared__ float sm[4];
    if ((tid & 31) == 0) sm[tid >> 5] = s;
    __syncthreads();
    float smax = fmaxf(fmaxf(sm[0], sm[1]), fmaxf(sm[2], sm[3]));

    const float* nrow = noise + (size_t)t * V_;
    float bn = -2.f; int bv = 0x7fffffff;
    for (int j = tid; j < NVB; j += 128) {
        if (ps[j] == smax) {
            int v = pi[j];
            float n = nrow[v];
            if (n > bn || (n == bn && v < bv)) { bn = n; bv = v; }
        }
    }
#pragma unroll
    for (int off = 16; off; off >>= 1) {
        float on = __shfl_xor_sync(0xffffffffu, bn, off);
        int   ov = __shfl_xor_sync(0xffffffffu, bv, off);
        if (on > bn || (on == bn && ov < bv)) { bn = on; bv = ov; }
    }
    __shared__ float nm[4]; __shared__ int vm[4];
    if ((tid & 31) == 0) { nm[tid >> 5] = bn; vm[tid >> 5] = bv; }
    __syncthreads();
    if (tid == 0) {
#pragma unroll
        for (int w = 1; w < 4; w++) {
            if (nm[w] > nm[0] || (nm[w] == nm[0] && vm[w] < vm[0])) { nm[0] = nm[w]; vm[0] = vm[w]; }
        }
        if (write_float) ((float*)out)[t] = (float)vm[0];
        else             ((int*)out)[t]   = vm[0];
    }
}

// ---------------- launcher ----------------
extern "C" void kernel_launch(void* const* d_in, const int* in_sizes, int n_in,
                              void* d_out, int out_size) {
    const int*   utt   = (const int*)d_in[0];
    const float* emb   = (const float*)d_in[1];
    const float* grad  = (const float*)d_in[2];
    const float* noise = (const float*)d_in[3];

    prep_kernel<<<BS_, 128>>>(utt, emb, grad);
    conv_kernel<<<(V_ + 7) / 8, 256>>>(emb);

    const long long SIMN = (long long)BS_ * V_;
    float* simptr;
    float* simscr;
    cudaGetSymbolAddress((void**)&simscr, g_sim_scratch);
    if ((long long)out_size == SIMN + BS_)      simptr = (float*)d_out + BS_;
    else if ((long long)out_size == SIMN)       simptr = (float*)d_out;
    else                                        simptr = simscr;

    cudaFuncSetAttribute(gemm_kernel, cudaFuncAttributeMaxDynamicSharedMemorySize, 98816);
    dim3 grid(BS_ / BN, NVB);
    gemm_kernel<<<grid, 512, 98816>>>(simptr, noise);

    if ((long long)out_size == SIMN + BS_)
        merge_kernel<<<BS_, 128>>>(noise, d_out, 1);
    else if (out_size == BS_)
        merge_kernel<<<BS_, 128>>>(noise, d_out, 0);
}

// round 16
// speedup vs baseline: 1.2288x; 1.0855x over previous
#include <cuda_runtime.h>
#include <cuda_fp16.h>
#include <cstdint>

#define V_    50257
#define VPAD  50304
#define NVB   393          // vocab blocks
#define BS_   512
#define D_    512
#define BM    128
#define BN    128
#define BKF   64
#define NCH   (D_/BKF)
#define PREPB 256          // fused kernel: first PREPB blocks do prep (2 tokens each)

__device__ __align__(16) uint2 g_pnh2[BS_*D_/4];        // pn fp16 pairs [t][k/4]
__device__ __align__(16) __half g_embh[(size_t)VPAD*D_]; // emb fp16 (rows >= V_ stay 0)
__device__ float g_inv_enorm[VPAD];
__device__ float g_sim_scratch[(size_t)BS_*V_];
__device__ float g_part_s[BS_*NVB];
__device__ int   g_part_i[BS_*NVB];

#define SW128(x) ((x) ^ (((x) >> 3) & 0x70))

__device__ __forceinline__ uint32_t smem_u32(const void* p){
    uint32_t a;
    asm("{ .reg .u64 t; cvta.to.shared.u64 t, %1; cvt.u32.u64 %0, t; }" : "=r"(a) : "l"(p));
    return a;
}
__device__ __forceinline__ uint32_t f16x2_of(float lo, float hi){
    __half2 h = __floats2half2_rn(lo, hi);
    return *(uint32_t*)&h;
}
__device__ __forceinline__ uint32_t ford(float f){   // order-preserving float->u32
    uint32_t b = __float_as_uint(f);
    return (b & 0x80000000u) ? ~b : (b | 0x80000000u);
}
__device__ __forceinline__ void ldsm4(uint32_t* r, uint32_t addr){
    asm volatile("ldmatrix.sync.aligned.m8n8.x4.shared.b16 {%0,%1,%2,%3}, [%4];"
        : "=r"(r[0]), "=r"(r[1]), "=r"(r[2]), "=r"(r[3]) : "r"(addr));
}
#define MMA16816(c, a, b0v, b1v) \
    asm volatile("mma.sync.aligned.m16n8k16.row.col.f32.f16.f16.f32 " \
        "{%0,%1,%2,%3}, {%4,%5,%6,%7}, {%8,%9}, {%0,%1,%2,%3};" \
        : "+f"((c)[0]), "+f"((c)[1]), "+f"((c)[2]), "+f"((c)[3]) \
        : "r"((a)[0]), "r"((a)[1]), "r"((a)[2]), "r"((a)[3]), "r"(b0v), "r"(b1v))
#define CPASYNC16(dst, src) \
    asm volatile("cp.async.cg.shared.global [%0], [%1], 16;" :: "r"(dst), "l"(src))
#define CPCOMMIT() asm volatile("cp.async.commit_group;" ::: "memory")
#define CPWAIT0()  asm volatile("cp.async.wait_group 0;" ::: "memory")
#define CPWAIT1()  asm volatile("cp.async.wait_group 1;" ::: "memory")

// ---------------- kernel 1: fused prep (tokens) + conv (emb fp16 + norms) ----------
__global__ void prep_conv_kernel(const int* __restrict__ utt, const float* __restrict__ emb,
                                 const float* __restrict__ grad) {
    const int b = blockIdx.x;
    if (b < PREPB) {
        // ---- prep: 2 tokens per block, 128 threads each ----
        const int half = threadIdx.x >> 7;     // 0 or 1
        const int tid  = threadIdx.x & 127;
        const int t = b * 2 + half;
        const int token = utt[t];
        float4 e = *(const float4*)(emb + (size_t)token * D_ + tid * 4);
        float4 g = *(const float4*)(grad + (size_t)t * D_ + tid * 4);
        float p0 = e.x + 0.4f * ((g.x > 0.f) ? 1.f : ((g.x < 0.f) ? -1.f : 0.f));
        float p1 = e.y + 0.4f * ((g.y > 0.f) ? 1.f : ((g.y < 0.f) ? -1.f : 0.f));
        float p2 = e.z + 0.4f * ((g.z > 0.f) ? 1.f : ((g.z < 0.f) ? -1.f : 0.f));
        float p3 = e.w + 0.4f * ((g.w > 0.f) ? 1.f : ((g.w < 0.f) ? -1.f : 0.f));
        float ss = p0*p0 + p1*p1 + p2*p2 + p3*p3;
#pragma unroll
        for (int off = 16; off; off >>= 1) ss += __shfl_xor_sync(0xffffffffu, ss, off);
        __shared__ float wsum[8];
        if ((tid & 31) == 0) wsum[half * 4 + (tid >> 5)] = ss;
        __syncthreads();
        float tot = wsum[half*4] + wsum[half*4+1] + wsum[half*4+2] + wsum[half*4+3];
        float inv = 1.f / fmaxf(sqrtf(tot), 1e-8f);
        p0 *= inv; p1 *= inv; p2 *= inv; p3 *= inv;
        g_pnh2[t * 128 + tid] = make_uint2(f16x2_of(p0, p1), f16x2_of(p2, p3));
    } else {
        // ---- conv: 8 emb rows per block ----
        const int row = (b - PREPB) * 8 + (threadIdx.x >> 5);
        const int lane = threadIdx.x & 31;
        if (row >= V_) return;
        const float4* src = (const float4*)(emb + (size_t)row * D_ + lane * 16);
        float4 a = src[0], b2 = src[1], c = src[2], d = src[3];
        float ss = a.x*a.x + a.y*a.y + a.z*a.z + a.w*a.w
                 + b2.x*b2.x + b2.y*b2.y + b2.z*b2.z + b2.w*b2.w
                 + c.x*c.x + c.y*c.y + c.z*c.z + c.w*c.w
                 + d.x*d.x + d.y*d.y + d.z*d.z + d.w*d.w;
        uint4 o0, o1;
        o0.x = f16x2_of(a.x, a.y);  o0.y = f16x2_of(a.z, a.w);
        o0.z = f16x2_of(b2.x, b2.y); o0.w = f16x2_of(b2.z, b2.w);
        o1.x = f16x2_of(c.x, c.y);  o1.y = f16x2_of(c.z, c.w);
        o1.z = f16x2_of(d.x, d.y);  o1.w = f16x2_of(d.z, d.w);
        uint4* dst = (uint4*)((char*)g_embh + (size_t)row * 1024 + lane * 32);
        dst[0] = o0; dst[1] = o1;
#pragma unroll
        for (int off = 16; off; off >>= 1) ss += __shfl_xor_sync(0xffffffffu, ss, off);
        if (lane == 0) g_inv_enorm[row] = 1.f / fmaxf(sqrtf(ss), 1e-8f);
    }
}

// ---------------- kernel 2: fp16 GEMM, 3-stage pipeline, fused argmax ----
__global__ void __launch_bounds__(512, 2) gemm_kernel(float* __restrict__ simout,
                                                      const float* __restrict__ noise) {
    extern __shared__ char smem[];
    const uint32_t sb = smem_u32(smem);
    const int tid = threadIdx.x;
    const int wid = tid >> 5, lane = tid & 31;
    const int tblk = blockIdx.x * BN;
    const int vblk = blockIdx.y * BM;

    float acc[2][4][4];
#pragma unroll
    for (int i = 0; i < 2; i++)
#pragma unroll
        for (int j = 0; j < 4; j++)
#pragma unroll
            for (int q = 0; q < 4; q++) acc[i][j][q] = 0.f;

    const int mw = (wid >> 2) * 32;
    const int nw = (wid & 3) * 32;
    const int a_row = (lane & 7) + ((lane >> 3) & 1) * 8;
    const int a_kb  = ((lane >> 4) & 1) * 16;
    const int b_row = (lane & 7) + ((lane >> 4) & 1) * 8;
    const int b_kb  = ((lane >> 3) & 1) * 16;

    const int lrow = tid >> 3;
    const int lseg = tid & 7;
    const uint32_t soff0 = SW128((uint32_t)(lrow * 128 + lseg * 16));
    const uint32_t soff1 = SW128((uint32_t)((lrow + 64) * 128 + lseg * 16));
    const size_t abase0 = (size_t)(vblk + lrow) * 1024 + lseg * 16;
    const size_t abase1 = (size_t)(vblk + lrow + 64) * 1024 + lseg * 16;
    const size_t bbase0 = (size_t)(tblk + lrow) * 1024 + lseg * 16;
    const size_t bbase1 = (size_t)(tblk + lrow + 64) * 1024 + lseg * 16;

    // ---- preamble: issue chunks 0 and 1 into stages 0 and 1 ----
#pragma unroll
    for (int pc = 0; pc < 2; pc++) {
        const uint32_t st = (uint32_t)(pc * 32768);
        const size_t kb = (size_t)pc * 128;
        CPASYNC16(sb + st + soff0,         (const char*)g_embh + abase0 + kb);
        CPASYNC16(sb + st + soff1,         (const char*)g_embh + abase1 + kb);
        CPASYNC16(sb + st + 16384 + soff0, (const char*)g_pnh2 + bbase0 + kb);
        CPASYNC16(sb + st + 16384 + soff1, (const char*)g_pnh2 + bbase1 + kb);
        CPCOMMIT();
    }

#pragma unroll
    for (int c = 0; c < NCH; c++) {
        if (c == NCH - 1) { CPWAIT0(); } else { CPWAIT1(); }
        __syncthreads();
        if (c + 2 < NCH) {
            const uint32_t nb = (uint32_t)(((c + 2) % 3) * 32768);
            const size_t kb = (size_t)(c + 2) * 128;
            CPASYNC16(sb + nb + soff0,         (const char*)g_embh + abase0 + kb);
            CPASYNC16(sb + nb + soff1,         (const char*)g_embh + abase1 + kb);
            CPASYNC16(sb + nb + 16384 + soff0, (const char*)g_pnh2 + bbase0 + kb);
            CPASYNC16(sb + nb + 16384 + soff1, (const char*)g_pnh2 + bbase1 + kb);
            CPCOMMIT();
        }
        const uint32_t AB = (uint32_t)((c % 3) * 32768), BB = AB + 16384;
#pragma unroll
        for (int s = 0; s < 4; s++) {
            const uint32_t akoff = (uint32_t)(s * 32 + a_kb);
            const uint32_t bkoff = (uint32_t)(s * 32 + b_kb);
            uint32_t ah[8], bh[8];
#pragma unroll
            for (int i = 0; i < 2; i++)
                ldsm4(&ah[i*4], sb + AB + SW128((uint32_t)((mw + i*16 + a_row) * 128) + akoff));
#pragma unroll
            for (int j2 = 0; j2 < 2; j2++)
                ldsm4(&bh[j2*4], sb + BB + SW128((uint32_t)((nw + j2*16 + b_row) * 128) + bkoff));
#pragma unroll
            for (int i = 0; i < 2; i++)
#pragma unroll
                for (int j = 0; j < 4; j++)
                    MMA16816(acc[i][j], &ah[i*4], bh[(j>>1)*4 + (j&1)*2], bh[(j>>1)*4 + (j&1)*2 + 1]);
        }
    }
    __syncthreads();

    // ---- inv norms + full C tile staged in one pass ----
    float* sInv = (float*)(smem + 98304);
    if (tid < 128) sInv[tid] = g_inv_enorm[vblk + tid];
    float* cs = (float*)smem;            // [128][132] floats = 67584 B
#pragma unroll
    for (int i = 0; i < 2; i++)
#pragma unroll
        for (int j = 0; j < 4; j++) {
            int v0 = mw + i * 16 + (lane >> 2);
            int tl = nw + j * 8 + (lane & 3) * 2;
            cs[ tl      * 132 + v0    ] = acc[i][j][0];
            cs[(tl + 1) * 132 + v0    ] = acc[i][j][1];
            cs[ tl      * 132 + v0 + 8] = acc[i][j][2];
            cs[(tl + 1) * 132 + v0 + 8] = acc[i][j][3];
        }
    __syncthreads();

    // ---- store + fused partial argmax (redux fast path): 8 iters x 16 token-rows ----
    const int v4 = lane * 4;
#pragma unroll
    for (int it = 0; it < 8; it++) {
        int tl = (tid >> 5) + it * 16;
        int gt = tblk + tl;
        float4 val = *(float4*)(cs + tl * 132 + v4);
        val.x *= sInv[v4];
        val.y *= sInv[v4 + 1];
        val.z *= sInv[v4 + 2];
        val.w *= sInv[v4 + 3];
        int gv = vblk + v4;
        // scalar stores: sim row base gt*V_ only 4B aligned (V_ odd)
        float* dst = simout + (size_t)gt * V_ + gv;
        if (gv     < V_) dst[0] = val.x;
        if (gv + 1 < V_) dst[1] = val.y;
        if (gv + 2 < V_) dst[2] = val.z;
        if (gv + 3 < V_) dst[3] = val.w;
        // per-lane best over its 4 v (noise only on exact ties; keeps smaller v on equal noise)
        const float* nrow = noise + (size_t)gt * V_;
        float fs = -3e38f; int fv = 0;
        float e[4] = {val.x, val.y, val.z, val.w};
#pragma unroll
        for (int u = 0; u < 4; u++) {
            float sv = (gv + u < V_) ? e[u] : -3e38f;
            if (sv > fs) { fs = sv; fv = gv + u; }
            else if (sv == fs && sv > -3e38f) {
                float n1 = nrow[fv], n2 = nrow[gv + u];
                if (n2 > n1) fv = gv + u;
            }
        }
        // warp reduce via redux: lane order == v order, so lowest tied lane = smallest v
        uint32_t key = ford(fs);
        uint32_t m = __reduce_max_sync(0xffffffffu, key);
        uint32_t mask = __ballot_sync(0xffffffffu, key == m);
        int winner;
        if (__popc(mask) > 1) {
            bool t = (key == m);
            uint32_t nk = t ? __float_as_uint(nrow[fv]) : 0u;   // noise >= 0: bits orderable
            uint32_t m2 = __reduce_max_sync(0xffffffffu, nk);
            uint32_t mask2 = __ballot_sync(0xffffffffu, t && nk == m2);
            winner = __ffs(mask2) - 1;
        } else {
            winner = __ffs(mask) - 1;
        }
        float wfs = __shfl_sync(0xffffffffu, fs, winner);
        int   wfv = __shfl_sync(0xffffffffu, fv, winner);
        if (lane == 0) {
            g_part_s[gt * NVB + blockIdx.y] = wfs;
            g_part_i[gt * NVB + blockIdx.y] = wfv;
        }
    }
}

// ---------------- kernel 3: merge partials ----------------
__global__ void merge_kernel(const float* __restrict__ noise,
                             void* __restrict__ out, int write_float) {
    const int t = blockIdx.x, tid = threadIdx.x;   // 128 threads
    const float* ps = g_part_s + t * NVB;
    const int*   pi = g_part_i + t * NVB;

    float s = -3e38f;
    for (int j = tid; j < NVB; j += 128) s = fmaxf(s, ps[j]);
#pragma unroll
    for (int off = 16; off; off >>= 1) s = fmaxf(s, __shfl_xor_sync(0xffffffffu, s, off));
    __shared__ float sm[4];
    if ((tid & 31) == 0) sm[tid >> 5] = s;
    __syncthreads();
    float smax = fmaxf(fmaxf(sm[0], sm[1]), fmaxf(sm[2], sm[3]));

    const float* nrow = noise + (size_t)t * V_;
    float bn = -2.f; int bv = 0x7fffffff;
    for (int j = tid; j < NVB; j += 128) {
        if (ps[j] == smax) {
            int v = pi[j];
            float n = nrow[v];
            if (n > bn || (n == bn && v < bv)) { bn = n; bv = v; }
        }
    }
#pragma unroll
    for (int off = 16; off; off >>= 1) {
        float on = __shfl_xor_sync(0xffffffffu, bn, off);
        int   ov = __shfl_xor_sync(0xffffffffu, bv, off);
        if (on > bn || (on == bn && ov < bv)) { bn = on; bv = ov; }
    }
    __shared__ float nm[4]; __shared__ int vm[4];
    if ((tid & 31) == 0) { nm[tid >> 5] = bn; vm[tid >> 5] = bv; }
    __syncthreads();
    if (tid == 0) {
#pragma unroll
        for (int w = 1; w < 4; w++) {
            if (nm[w] > nm[0] || (nm[w] == nm[0] && vm[w] < vm[0])) { nm[0] = nm[w]; vm[0] = vm[w]; }
        }
        if (write_float) ((float*)out)[t] = (float)vm[0];
        else             ((int*)out)[t]   = vm[0];
    }
}

// ---------------- launcher ----------------
extern "C" void kernel_launch(void* const* d_in, const int* in_sizes, int n_in,
                              void* d_out, int out_size) {
    const int*   utt   = (const int*)d_in[0];
    const float* emb   = (const float*)d_in[1];
    const float* grad  = (const float*)d_in[2];
    const float* noise = (const float*)d_in[3];

    const int convb = (V_ + 7) / 8;
    prep_conv_kernel<<<PREPB + convb, 256>>>(utt, emb, grad);

    const long long SIMN = (long long)BS_ * V_;
    float* simptr;
    float* simscr;
    cudaGetSymbolAddress((void**)&simscr, g_sim_scratch);
    if ((long long)out_size == SIMN + BS_)      simptr = (float*)d_out + BS_;
    else if ((long long)out_size == SIMN)       simptr = (float*)d_out;
    else                                        simptr = simscr;

    cudaFuncSetAttribute(gemm_kernel, cudaFuncAttributeMaxDynamicSharedMemorySize, 98816);
    dim3 grid(BS_ / BN, NVB);
    gemm_kernel<<<grid, 512, 98816>>>(simptr, noise);

    if ((long long)out_size == SIMN + BS_)
        merge_kernel<<<BS_, 128>>>(noise, d_out, 1);
    else if (out_size == BS_)
        merge_kernel<<<BS_, 128>>>(noise, d_out, 0);
}